// round 13
// baseline (speedup 1.0000x reference)
#include <cuda_runtime.h>
#include <cuda_bf16.h>
#include <cuda_fp16.h>
#include <stdint.h>

// Problem constants (fixed by the dataset)
#define NMAX   100000
#define EMAX   1600000
#define D      128
#define SCANB  1024
#define NCHUNK 4

// ---------------- device scratch (allocation-free rule: __device__ globals) ----
__device__ __half g_zhA[NMAX * D];    // fp16 message term, layers 0 & 2
__device__ __half g_zhB[NMAX * D];    // fp16 message term, layer 1
__device__ float g_y[NMAX * D];
__device__ float g_h1[NMAX * D];
__device__ float g_h2[NMAX * D];
__device__ int   g_col[EMAX];
__device__ int   g_rowptr[NMAX + 1];
__device__ int   g_cursor[NMAX];
__device__ int   g_deg[NMAX];
__device__ float g_invdeg[NMAX];
__device__ int   g_bsums[1024];
// pre-converted, pre-swizzled W tile images (split-bf16), one per layer
__device__ __align__(16) char g_wimg[3][131072];

// ---------------- CSR build ---------------------------------------------------
__global__ void zero_deg_kernel(int* deg, int n) {
    int i = blockIdx.x * blockDim.x + threadIdx.x;
    if (i < n) deg[i] = 0;
}

__global__ void hist_kernel(const int* __restrict__ dst, int* __restrict__ deg, int e) {
    int i = blockIdx.x * blockDim.x + threadIdx.x;
    if (i < e) atomicAdd(&deg[dst[i]], 1);
}

__global__ void invdeg_kernel(const int* __restrict__ deg, float* __restrict__ invdeg, int n) {
    int i = blockIdx.x * blockDim.x + threadIdx.x;
    if (i < n) {
        int d = deg[i];
        invdeg[i] = 1.0f / (float)(d > 0 ? d : 1);
    }
}

__global__ void scanA_kernel(const int* __restrict__ deg, int* __restrict__ excl,
                             int* __restrict__ bsums, int n) {
    __shared__ int sh[SCANB];
    int tid = threadIdx.x;
    int i = blockIdx.x * SCANB + tid;
    int v = (i < n) ? deg[i] : 0;
    sh[tid] = v;
    __syncthreads();
    for (int off = 1; off < SCANB; off <<= 1) {
        int t = (tid >= off) ? sh[tid - off] : 0;
        __syncthreads();
        sh[tid] += t;
        __syncthreads();
    }
    if (i < n) excl[i] = sh[tid] - v;
    if (tid == SCANB - 1) bsums[blockIdx.x] = sh[tid];
}

__global__ void scanB_kernel(int* __restrict__ bsums, int nb) {
    __shared__ int sh[1024];
    int tid = threadIdx.x;
    int v = (tid < nb) ? bsums[tid] : 0;
    sh[tid] = v;
    __syncthreads();
    for (int off = 1; off < 1024; off <<= 1) {
        int t = (tid >= off) ? sh[tid - off] : 0;
        __syncthreads();
        sh[tid] += t;
        __syncthreads();
    }
    if (tid < nb) bsums[tid] = sh[tid] - v;
}

__global__ void scanC_kernel(int* __restrict__ rowptr, int* __restrict__ cursor,
                             const int* __restrict__ bsums, int n, int e) {
    int i = blockIdx.x * blockDim.x + threadIdx.x;
    if (i < n) {
        int r = rowptr[i] + bsums[i >> 10];
        rowptr[i] = r;
        cursor[i] = r;
    }
    if (i == 0) rowptr[n] = e;
}

__global__ void scatter_kernel(const int* __restrict__ src,
                               const int* __restrict__ dst,
                               int* __restrict__ cursor, int* __restrict__ col, int e) {
    int i = blockIdx.x * blockDim.x + threadIdx.x;
    if (i < e) {
        int d = dst[i];
        int s = src[i];
        int pos = atomicAdd(&cursor[d], 1);
        col[pos] = s;
    }
}

// ---------------- shared helpers -----------------------------------------------
__device__ __forceinline__ uint32_t sw_off(int row, int k) {
    int chunk = k >> 3;
    int swc = chunk ^ (row & 7);
    return (uint32_t)(row * 512 + swc * 16 + (k & 7) * 2);
}

__device__ __forceinline__ unsigned long long pack2x2(__nv_bfloat162 p0, __nv_bfloat162 p1) {
    unsigned int u0 = *(unsigned int*)&p0;
    unsigned int u1 = *(unsigned int*)&p1;
    return (unsigned long long)u0 | ((unsigned long long)u1 << 32);
}

__device__ __forceinline__ void split_f4(float4 v, unsigned long long& hi8,
                                         unsigned long long& lo8) {
    __nv_bfloat162 h01 = __floats2bfloat162_rn(v.x, v.y);
    __nv_bfloat162 h23 = __floats2bfloat162_rn(v.z, v.w);
    float r0 = v.x - __low2float(h01);
    float r1 = v.y - __high2float(h01);
    float r2 = v.z - __low2float(h23);
    float r3 = v.w - __high2float(h23);
    __nv_bfloat162 l01 = __floats2bfloat162_rn(r0, r1);
    __nv_bfloat162 l23 = __floats2bfloat162_rn(r2, r3);
    hi8 = pack2x2(h01, h23);
    lo8 = pack2x2(l01, l23);
}

__device__ __forceinline__ uint32_t smem_u32(const void* p) {
    uint32_t a;
    asm("{ .reg .u64 t; cvta.to.shared.u64 t, %1; cvt.u32.u64 %0, t; }" : "=r"(a) : "l"(p));
    return a;
}

#define LDSM_X4(d0, d1, d2, d3, addr) \
    asm volatile("ldmatrix.sync.aligned.m8n8.x4.shared.b16 {%0,%1,%2,%3}, [%4];" \
                 : "=r"(d0), "=r"(d1), "=r"(d2), "=r"(d3) : "r"(addr))

#define MMA_BF16(d, a, b) \
    asm volatile("mma.sync.aligned.m16n8k16.row.col.f32.bf16.bf16.f32 " \
                 "{%0,%1,%2,%3}, {%4,%5,%6,%7}, {%8,%9}, {%0,%1,%2,%3};" \
                 : "+f"((d)[0]), "+f"((d)[1]), "+f"((d)[2]), "+f"((d)[3]) \
                 : "r"((a)[0]), "r"((a)[1]), "r"((a)[2]), "r"((a)[3]), \
                   "r"((b)[0]), "r"((b)[1]))

// ---------------- W pre-convert: fp32 -> split-bf16, swizzled tile image -------
__global__ __launch_bounds__(256) void convert_w_kernel(
    const float* __restrict__ Wl, const float* __restrict__ Wr, char* __restrict__ img)
{
    int idx = blockIdx.x * blockDim.x + threadIdx.x;   // 0..8191
    if (idx >= 8192) return;
    int j = idx >> 5;
    int q = idx & 31;
    const float* srcw = (j < 128) ? (Wl + (size_t)j * D + q * 4)
                                  : (Wr + (size_t)(j - 128) * D + q * 4);
    float4 v = *(const float4*)srcw;
    unsigned long long hi8, lo8;
    split_f4(v, hi8, lo8);
    *(unsigned long long*)(img + sw_off(j, q * 4))       = hi8;
    *(unsigned long long*)(img + sw_off(j, 128 + q * 4)) = lo8;
}

// ---------------- tensor-core transform (persistent, double-buffered) ----------
#define TF_A0_OFF  0
#define TF_A1_OFF  32768
#define TF_B_OFF   65536
#define TF_SMEM_SZ 196608
#define TILE_M     64

__global__ __launch_bounds__(512) void transform_mma_kernel(
    const float* __restrict__ h,
    const char* __restrict__ wimg,
    const float* __restrict__ bias,
    __half* __restrict__ zh, float* __restrict__ yo, int n,
    int tile_beg, int tile_end)
{
    extern __shared__ char smem[];
    const uint32_t sbase = smem_u32(smem);
    const uint32_t sb = sbase + TF_B_OFF;
    int tid = threadIdx.x;

    // ---- load pre-converted W tile (131072 B straight copy) ----
    {
        const float4* wsrc = (const float4*)wimg;
        float4* bdst = (float4*)(smem + TF_B_OFF);
#pragma unroll
        for (int it = 0; it < 16; it++)
            bdst[tid + it * 512] = wsrc[tid + it * 512];
    }

    int wid = tid >> 5;
    int lane = tid & 31;
    int wm = wid >> 3;
    int wn = wid & 7;
    int R = wm * 32;
    int C = wn * 32;

    int a_r = (lane & 7) + ((lane >> 3) & 1) * 8;
    int a_k = ((lane >> 4) & 1) * 8;
    int b_n = (lane & 7) + ((lane >> 4) & 1) * 8;
    int b_k = ((lane >> 3) & 1) * 8;
    int g  = lane >> 2;
    int tg = lane & 3;

    int pr[4], pq[4];
#pragma unroll
    for (int it = 0; it < 4; it++) {
        int idx = tid + it * 512;
        pr[it] = idx >> 5;
        pq[it] = idx & 31;
    }

    bool is_y = (C >= 128);
    float bv0[4], bv1[4];
    if (is_y) {
#pragma unroll
        for (int nt = 0; nt < 4; nt++) {
            int yc = C - 128 + nt * 8 + tg * 2;
            bv0[nt] = __ldg(&bias[yc]);
            bv1[nt] = __ldg(&bias[yc + 1]);
        }
    }

    // ---- prologue: prefetch + convert first tile into buffer 0 ----
    float4 pf[4];
    int tile0 = tile_beg + blockIdx.x;
    {
        int row0 = tile0 * TILE_M;
#pragma unroll
        for (int it = 0; it < 4; it++) {
            int grow = row0 + pr[it];
            pf[it] = (tile0 < tile_end && grow < n)
                   ? *(const float4*)(h + (size_t)grow * D + pq[it] * 4)
                   : make_float4(0.f, 0.f, 0.f, 0.f);
        }
#pragma unroll
        for (int it = 0; it < 4; it++) {
            unsigned long long hi8, lo8;
            split_f4(pf[it], hi8, lo8);
            *(unsigned long long*)(smem + TF_A0_OFF + sw_off(pr[it], pq[it] * 4))       = hi8;
            *(unsigned long long*)(smem + TF_A0_OFF + sw_off(pr[it], 128 + pq[it] * 4)) = lo8;
        }
    }

    int cur = 0;
    for (int tile = tile0; tile < tile_end; tile += gridDim.x) {
        __syncthreads();
        const uint32_t sa = sbase + (cur ? TF_A1_OFF : TF_A0_OFF);
        const uint32_t sa_nxt = sbase + (cur ? TF_A0_OFF : TF_A1_OFF);
        int nxt = tile + gridDim.x;
        bool have_nxt = (nxt < tile_end);

        if (have_nxt) {
            int nrow0 = nxt * TILE_M;
#pragma unroll
            for (int it = 0; it < 4; it++) {
                int grow = nrow0 + pr[it];
                pf[it] = (grow < n)
                       ? *(const float4*)(h + (size_t)grow * D + pq[it] * 4)
                       : make_float4(0.f, 0.f, 0.f, 0.f);
            }
        }

        float acc[2][4][4];
#pragma unroll
        for (int mt = 0; mt < 2; mt++)
#pragma unroll
            for (int nt = 0; nt < 4; nt++)
#pragma unroll
                for (int i = 0; i < 4; i++) acc[mt][nt][i] = 0.f;

#pragma unroll
        for (int kc = 0; kc < 8; kc++) {
            int ka_hi = kc * 16 + a_k;
            int ka_lo = 128 + ka_hi;
            int kb_hi = kc * 16 + b_k;
            int kb_lo = 128 + kb_hi;

            uint32_t ahi[2][4], alo[2][4];
#pragma unroll
            for (int mt = 0; mt < 2; mt++) {
                uint32_t addr = sa + sw_off(R + mt * 16 + a_r, ka_hi);
                LDSM_X4(ahi[mt][0], ahi[mt][1], ahi[mt][2], ahi[mt][3], addr);
                addr = sa + sw_off(R + mt * 16 + a_r, ka_lo);
                LDSM_X4(alo[mt][0], alo[mt][1], alo[mt][2], alo[mt][3], addr);
            }
            uint32_t bhi[4][2];
#pragma unroll
            for (int p = 0; p < 2; p++) {
                uint32_t addr = sb + sw_off(C + p * 16 + b_n, kb_hi);
                uint32_t d0, d1, d2, d3;
                LDSM_X4(d0, d1, d2, d3, addr);
                bhi[p * 2][0] = d0;     bhi[p * 2][1] = d1;
                bhi[p * 2 + 1][0] = d2; bhi[p * 2 + 1][1] = d3;
            }
#pragma unroll
            for (int mt = 0; mt < 2; mt++)
#pragma unroll
                for (int nt = 0; nt < 4; nt++) {
                    MMA_BF16(acc[mt][nt], ahi[mt], bhi[nt]);
                    MMA_BF16(acc[mt][nt], alo[mt], bhi[nt]);
                }
            uint32_t blo[4][2];
#pragma unroll
            for (int p = 0; p < 2; p++) {
                uint32_t addr = sb + sw_off(C + p * 16 + b_n, kb_lo);
                uint32_t d0, d1, d2, d3;
                LDSM_X4(d0, d1, d2, d3, addr);
                blo[p * 2][0] = d0;     blo[p * 2][1] = d1;
                blo[p * 2 + 1][0] = d2; blo[p * 2 + 1][1] = d3;
            }
#pragma unroll
            for (int mt = 0; mt < 2; mt++)
#pragma unroll
                for (int nt = 0; nt < 4; nt++)
                    MMA_BF16(acc[mt][nt], ahi[mt], blo[nt]);
        }

        if (have_nxt) {
#pragma unroll
            for (int it = 0; it < 4; it++) {
                unsigned long long hi8, lo8;
                split_f4(pf[it], hi8, lo8);
                *(unsigned long long*)((char*)smem + (sa_nxt - sbase) + sw_off(pr[it], pq[it] * 4))       = hi8;
                *(unsigned long long*)((char*)smem + (sa_nxt - sbase) + sw_off(pr[it], 128 + pq[it] * 4)) = lo8;
            }
        }

        int row0 = tile * TILE_M;
#pragma unroll
        for (int mt = 0; mt < 2; mt++) {
            int r0g = row0 + R + mt * 16 + g;
            int r1g = r0g + 8;
            bool ok0 = (r0g < n), ok1 = (r1g < n);
            if (!is_y) {
#pragma unroll
                for (int nt = 0; nt < 4; nt++) {
                    int colg = C + nt * 8 + tg * 2;
                    if (ok0) *(__half2*)(zh + (size_t)r0g * D + colg) =
                        __floats2half2_rn(acc[mt][nt][0], acc[mt][nt][1]);
                    if (ok1) *(__half2*)(zh + (size_t)r1g * D + colg) =
                        __floats2half2_rn(acc[mt][nt][2], acc[mt][nt][3]);
                }
            } else {
#pragma unroll
                for (int nt = 0; nt < 4; nt++) {
                    int yc = C - 128 + nt * 8 + tg * 2;
                    if (ok0) *(float2*)(yo + (size_t)r0g * D + yc) =
                        make_float2(acc[mt][nt][0] + bv0[nt], acc[mt][nt][1] + bv1[nt]);
                    if (ok1) *(float2*)(yo + (size_t)r1g * D + yc) =
                        make_float2(acc[mt][nt][2] + bv0[nt], acc[mt][nt][3] + bv1[nt]);
                }
            }
        }
        cur ^= 1;
    }
}

// ---------------- aggregation: out[i] = act(sum zh[col] * invdeg + y) ----------
__global__ __launch_bounds__(256) void aggregate_kernel(
    const __half* __restrict__ zh, const float* __restrict__ y,
    const int* __restrict__ rowptr, const int* __restrict__ col,
    const float* __restrict__ invdeg, float* __restrict__ out,
    int node_beg, int node_end, int do_relu)
{
    int warp = node_beg + (int)((blockIdx.x * blockDim.x + threadIdx.x) >> 5);
    int lane = threadIdx.x & 31;
    if (warp >= node_end) return;

    int beg = rowptr[warp];
    int end = rowptr[warp + 1];

    float4 acc = make_float4(0.f, 0.f, 0.f, 0.f);
    for (int e = beg; e < end; e++) {
        int s = __ldg(&col[e]);
        uint2 raw = *(const uint2*)(zh + (size_t)s * D + lane * 4);
        float2 f0 = __half22float2(*(__half2*)&raw.x);
        float2 f1 = __half22float2(*(__half2*)&raw.y);
        acc.x += f0.x; acc.y += f0.y; acc.z += f1.x; acc.w += f1.y;
    }
    float inv = invdeg[warp];
    float4 yv = *(const float4*)(y + (size_t)warp * D + lane * 4);
    float4 o;
    o.x = fmaf(acc.x, inv, yv.x);
    o.y = fmaf(acc.y, inv, yv.y);
    o.z = fmaf(acc.z, inv, yv.z);
    o.w = fmaf(acc.w, inv, yv.w);
    if (do_relu) {
        o.x = fmaxf(o.x, 0.f); o.y = fmaxf(o.y, 0.f);
        o.z = fmaxf(o.z, 0.f); o.w = fmaxf(o.w, 0.f);
    }
    *(float4*)(out + (size_t)warp * D + lane * 4) = o;
}

// ---------------- launch -------------------------------------------------------
extern "C" void kernel_launch(void* const* d_in, const int* in_sizes, int n_in,
                              void* d_out, int out_size) {
    const float* x  = (const float*)d_in[0];
    const int*   ei = (const int*)d_in[1];      // int32 (JAX downcasts int64 w/o x64)
    const float* Wl[3] = {(const float*)d_in[2], (const float*)d_in[5], (const float*)d_in[8]};
    const float* Wr[3] = {(const float*)d_in[3], (const float*)d_in[6], (const float*)d_in[9]};
    const float* bb[3] = {(const float*)d_in[4], (const float*)d_in[7], (const float*)d_in[10]};
    float* out = (float*)d_out;

    int n = in_sizes[0] / D;        // 100000
    int e = in_sizes[1] / 2;        // 1600000
    const int* src = ei;
    const int* dst = ei + e;

    float *p_y, *p_h1, *p_h2, *p_invdeg;
    __half *p_zhA, *p_zhB;
    int *p_col, *p_rowptr, *p_cursor, *p_deg, *p_bsums;
    char* p_wimg;
    cudaGetSymbolAddress((void**)&p_zhA,    g_zhA);
    cudaGetSymbolAddress((void**)&p_zhB,    g_zhB);
    cudaGetSymbolAddress((void**)&p_y,      g_y);
    cudaGetSymbolAddress((void**)&p_h1,     g_h1);
    cudaGetSymbolAddress((void**)&p_h2,     g_h2);
    cudaGetSymbolAddress((void**)&p_invdeg, g_invdeg);
    cudaGetSymbolAddress((void**)&p_col,    g_col);
    cudaGetSymbolAddress((void**)&p_rowptr, g_rowptr);
    cudaGetSymbolAddress((void**)&p_cursor, g_cursor);
    cudaGetSymbolAddress((void**)&p_deg,    g_deg);
    cudaGetSymbolAddress((void**)&p_bsums,  g_bsums);
    cudaGetSymbolAddress((void**)&p_wimg,   g_wimg);

    // one-time infra (no device memory involved)
    static cudaStream_t s_side = nullptr;
    static cudaEvent_t ev_fork = nullptr, ev_t1 = nullptr, ev_t2 = nullptr;
    static cudaEvent_t ev_a1[NCHUNK], ev_a2[NCHUNK];
    if (!s_side) {
        cudaFuncSetAttribute(transform_mma_kernel,
                             cudaFuncAttributeMaxDynamicSharedMemorySize, TF_SMEM_SZ);
        cudaStreamCreateWithFlags(&s_side, cudaStreamNonBlocking);
        cudaEventCreateWithFlags(&ev_fork, cudaEventDisableTiming);
        cudaEventCreateWithFlags(&ev_t1,   cudaEventDisableTiming);
        cudaEventCreateWithFlags(&ev_t2,   cudaEventDisableTiming);
        for (int c = 0; c < NCHUNK; c++) {
            cudaEventCreateWithFlags(&ev_a1[c], cudaEventDisableTiming);
            cudaEventCreateWithFlags(&ev_a2[c], cudaEventDisableTiming);
        }
    }

    int nb_n = (n + 255) / 256;
    int nb_e = (e + 255) / 256;
    int nb_scan = (n + SCANB - 1) / SCANB;
    int ntiles = (n + TILE_M - 1) / TILE_M;        // 1563
    int nb_ag_full = (n * 32 + 255) / 256;

    // tile-aligned chunk boundaries
    int tpc = (ntiles + NCHUNK - 1) / NCHUNK;      // 391
    int tb[NCHUNK + 1], nb_[NCHUNK + 1];
    for (int c = 0; c <= NCHUNK; c++) {
        int t = c * tpc; if (t > ntiles) t = ntiles;
        tb[c] = t;
        int nn = t * TILE_M; if (nn > n) nn = n;
        nb_[c] = nn;
    }

    // ---- fork: CSR build on side stream ----
    cudaEventRecord(ev_fork, 0);
    cudaStreamWaitEvent(s_side, ev_fork, 0);
    zero_deg_kernel<<<nb_n, 256, 0, s_side>>>(p_deg, n);
    hist_kernel<<<nb_e, 256, 0, s_side>>>(dst, p_deg, e);
    invdeg_kernel<<<nb_n, 256, 0, s_side>>>(p_deg, p_invdeg, n);
    scanA_kernel<<<nb_scan, SCANB, 0, s_side>>>(p_deg, p_rowptr, p_bsums, n);
    scanB_kernel<<<1, 1024, 0, s_side>>>(p_bsums, nb_scan);
    scanC_kernel<<<nb_n, 256, 0, s_side>>>(p_rowptr, p_cursor, p_bsums, n, e);
    scatter_kernel<<<nb_e, 256, 0, s_side>>>(src, dst, p_cursor, p_col, e);

    // ---- main: W convert + transform1 (full, writes zhA) ----
    for (int l = 0; l < 3; l++)
        convert_w_kernel<<<32, 256>>>(Wl[l], Wr[l], p_wimg + (size_t)l * 131072);
    transform_mma_kernel<<<148, 512, TF_SMEM_SZ>>>(x, p_wimg, bb[0],
                                                   p_zhA, p_y, n, 0, ntiles);
    cudaEventRecord(ev_t1, 0);

    // ---- side: aggregate1 chunks (reads zhA; after CSR in-order + transform1) --
    cudaStreamWaitEvent(s_side, ev_t1, 0);
    for (int c = 0; c < NCHUNK; c++) {
        int cn = nb_[c + 1] - nb_[c];
        if (cn > 0) {
            int blocks = (cn * 32 + 255) / 256;
            aggregate_kernel<<<blocks, 256, 0, s_side>>>(p_zhA, p_y, p_rowptr, p_col,
                                                         p_invdeg, p_h1, nb_[c], nb_[c + 1], 1);
        }
        cudaEventRecord(ev_a1[c], s_side);
    }

    // ---- main: transform2 chunks (reads h1 chunk, writes zhB — no race w/ agg1) --
    for (int c = 0; c < NCHUNK; c++) {
        cudaStreamWaitEvent(0, ev_a1[c], 0);
        int tiles = tb[c + 1] - tb[c];
        if (tiles <= 0) continue;
        int grid = tiles < 148 ? tiles : 148;
        transform_mma_kernel<<<grid, 512, TF_SMEM_SZ>>>(p_h1, p_wimg + 131072, bb[1],
                                                        p_zhB, p_y, n, tb[c], tb[c + 1]);
    }
    cudaEventRecord(ev_t2, 0);

    // ---- side: aggregate2 chunks (reads zhB) ----
    cudaStreamWaitEvent(s_side, ev_t2, 0);
    for (int c = 0; c < NCHUNK; c++) {
        int cn = nb_[c + 1] - nb_[c];
        if (cn > 0) {
            int blocks = (cn * 32 + 255) / 256;
            aggregate_kernel<<<blocks, 256, 0, s_side>>>(p_zhB, p_y, p_rowptr, p_col,
                                                         p_invdeg, p_h2, nb_[c], nb_[c + 1], 1);
        }
        cudaEventRecord(ev_a2[c], s_side);
    }

    // ---- main: transform3 chunks (writes zhA — agg2 reads zhB, safe), agg3 ----
    for (int c = 0; c < NCHUNK; c++) {
        cudaStreamWaitEvent(0, ev_a2[c], 0);
        int tiles = tb[c + 1] - tb[c];
        if (tiles <= 0) continue;
        int grid = tiles < 148 ? tiles : 148;
        transform_mma_kernel<<<grid, 512, TF_SMEM_SZ>>>(p_h2, p_wimg + 2 * 131072, bb[2],
                                                        p_zhA, p_y, n, tb[c], tb[c + 1]);
    }
    aggregate_kernel<<<nb_ag_full, 256>>>(p_zhA, p_y, p_rowptr, p_col, p_invdeg,
                                          out, 0, n, 0);
}

// round 14
// speedup vs baseline: 1.0804x; 1.0804x over previous
#include <cuda_runtime.h>
#include <cuda_bf16.h>
#include <cuda_fp16.h>
#include <stdint.h>

// Problem constants (fixed by the dataset)
#define NMAX   100000
#define EMAX   1600000
#define D      128
#define SCANB  1024

// ---------------- device scratch (allocation-free rule: __device__ globals) ----
__device__ __half g_zh[NMAX * D];     // fp16 message term (gathered by aggregate)
__device__ float g_y[NMAX * D];
__device__ float g_h1[NMAX * D];
__device__ float g_h2[NMAX * D];
__device__ int   g_col[EMAX];
__device__ int   g_rowptr[NMAX + 1];
__device__ int   g_cursor[NMAX];
__device__ int   g_deg[NMAX];
__device__ float g_invdeg[NMAX];
__device__ int   g_bsums[1024];
// pre-converted, pre-swizzled W tile images (split-bf16), one per layer
__device__ __align__(16) char g_wimg[3][131072];

// ---------------- CSR build ---------------------------------------------------
__global__ void zero_deg_kernel(int* deg, int n) {
    int i = blockIdx.x * blockDim.x + threadIdx.x;
    if (i < n) deg[i] = 0;
}

__global__ void hist_kernel(const int* __restrict__ dst, int* __restrict__ deg, int e) {
    int i = blockIdx.x * blockDim.x + threadIdx.x;
    if (i < e) atomicAdd(&deg[dst[i]], 1);
}

__global__ void invdeg_kernel(const int* __restrict__ deg, float* __restrict__ invdeg, int n) {
    int i = blockIdx.x * blockDim.x + threadIdx.x;
    if (i < n) {
        int d = deg[i];
        invdeg[i] = 1.0f / (float)(d > 0 ? d : 1);
    }
}

__global__ void scanA_kernel(const int* __restrict__ deg, int* __restrict__ excl,
                             int* __restrict__ bsums, int n) {
    __shared__ int sh[SCANB];
    int tid = threadIdx.x;
    int i = blockIdx.x * SCANB + tid;
    int v = (i < n) ? deg[i] : 0;
    sh[tid] = v;
    __syncthreads();
    for (int off = 1; off < SCANB; off <<= 1) {
        int t = (tid >= off) ? sh[tid - off] : 0;
        __syncthreads();
        sh[tid] += t;
        __syncthreads();
    }
    if (i < n) excl[i] = sh[tid] - v;
    if (tid == SCANB - 1) bsums[blockIdx.x] = sh[tid];
}

__global__ void scanB_kernel(int* __restrict__ bsums, int nb) {
    __shared__ int sh[1024];
    int tid = threadIdx.x;
    int v = (tid < nb) ? bsums[tid] : 0;
    sh[tid] = v;
    __syncthreads();
    for (int off = 1; off < 1024; off <<= 1) {
        int t = (tid >= off) ? sh[tid - off] : 0;
        __syncthreads();
        sh[tid] += t;
        __syncthreads();
    }
    if (tid < nb) bsums[tid] = sh[tid] - v;
}

__global__ void scanC_kernel(int* __restrict__ rowptr, int* __restrict__ cursor,
                             const int* __restrict__ bsums, int n, int e) {
    int i = blockIdx.x * blockDim.x + threadIdx.x;
    if (i < n) {
        int r = rowptr[i] + bsums[i >> 10];
        rowptr[i] = r;
        cursor[i] = r;
    }
    if (i == 0) rowptr[n] = e;
}

__global__ void scatter_kernel(const int* __restrict__ src,
                               const int* __restrict__ dst,
                               int* __restrict__ cursor, int* __restrict__ col, int e) {
    int i = blockIdx.x * blockDim.x + threadIdx.x;
    if (i < e) {
        int d = dst[i];
        int s = src[i];
        int pos = atomicAdd(&cursor[d], 1);
        col[pos] = s;
    }
}

// ---------------- shared helpers -----------------------------------------------
__device__ __forceinline__ uint32_t sw_off(int row, int k) {
    int chunk = k >> 3;
    int swc = chunk ^ (row & 7);
    return (uint32_t)(row * 512 + swc * 16 + (k & 7) * 2);
}

__device__ __forceinline__ unsigned long long pack2x2(__nv_bfloat162 p0, __nv_bfloat162 p1) {
    unsigned int u0 = *(unsigned int*)&p0;
    unsigned int u1 = *(unsigned int*)&p1;
    return (unsigned long long)u0 | ((unsigned long long)u1 << 32);
}

__device__ __forceinline__ void split_f4(float4 v, unsigned long long& hi8,
                                         unsigned long long& lo8) {
    __nv_bfloat162 h01 = __floats2bfloat162_rn(v.x, v.y);
    __nv_bfloat162 h23 = __floats2bfloat162_rn(v.z, v.w);
    float r0 = v.x - __low2float(h01);
    float r1 = v.y - __high2float(h01);
    float r2 = v.z - __low2float(h23);
    float r3 = v.w - __high2float(h23);
    __nv_bfloat162 l01 = __floats2bfloat162_rn(r0, r1);
    __nv_bfloat162 l23 = __floats2bfloat162_rn(r2, r3);
    hi8 = pack2x2(h01, h23);
    lo8 = pack2x2(l01, l23);
}

__device__ __forceinline__ uint32_t smem_u32(const void* p) {
    uint32_t a;
    asm("{ .reg .u64 t; cvta.to.shared.u64 t, %1; cvt.u32.u64 %0, t; }" : "=r"(a) : "l"(p));
    return a;
}

#define LDSM_X4(d0, d1, d2, d3, addr) \
    asm volatile("ldmatrix.sync.aligned.m8n8.x4.shared.b16 {%0,%1,%2,%3}, [%4];" \
                 : "=r"(d0), "=r"(d1), "=r"(d2), "=r"(d3) : "r"(addr))

#define MMA_BF16(d, a, b) \
    asm volatile("mma.sync.aligned.m16n8k16.row.col.f32.bf16.bf16.f32 " \
                 "{%0,%1,%2,%3}, {%4,%5,%6,%7}, {%8,%9}, {%0,%1,%2,%3};" \
                 : "+f"((d)[0]), "+f"((d)[1]), "+f"((d)[2]), "+f"((d)[3]) \
                 : "r"((a)[0]), "r"((a)[1]), "r"((a)[2]), "r"((a)[3]), \
                   "r"((b)[0]), "r"((b)[1]))

// ---------------- W pre-convert: fp32 -> split-bf16, swizzled tile image -------
__global__ __launch_bounds__(256) void convert_w_kernel(
    const float* __restrict__ Wl, const float* __restrict__ Wr, char* __restrict__ img)
{
    int idx = blockIdx.x * blockDim.x + threadIdx.x;   // 0..8191
    if (idx >= 8192) return;
    int j = idx >> 5;
    int q = idx & 31;
    const float* srcw = (j < 128) ? (Wl + (size_t)j * D + q * 4)
                                  : (Wr + (size_t)(j - 128) * D + q * 4);
    float4 v = *(const float4*)srcw;
    unsigned long long hi8, lo8;
    split_f4(v, hi8, lo8);
    *(unsigned long long*)(img + sw_off(j, q * 4))       = hi8;
    *(unsigned long long*)(img + sw_off(j, 128 + q * 4)) = lo8;
}

// ---------------- tensor-core transform (persistent, double-buffered) ----------
#define TF_A0_OFF  0
#define TF_A1_OFF  32768
#define TF_B_OFF   65536
#define TF_SMEM_SZ 196608
#define TILE_M     64

__global__ __launch_bounds__(512) void transform_mma_kernel(
    const float* __restrict__ h,
    const char* __restrict__ wimg,
    const float* __restrict__ bias,
    __half* __restrict__ zh, float* __restrict__ yo, int n, int ntiles)
{
    extern __shared__ char smem[];
    const uint32_t sbase = smem_u32(smem);
    const uint32_t sb = sbase + TF_B_OFF;
    int tid = threadIdx.x;

    // ---- load pre-converted W tile (131072 B straight copy) ----
    {
        const float4* wsrc = (const float4*)wimg;
        float4* bdst = (float4*)(smem + TF_B_OFF);
#pragma unroll
        for (int it = 0; it < 16; it++)
            bdst[tid + it * 512] = wsrc[tid + it * 512];
    }

    int wid = tid >> 5;
    int lane = tid & 31;
    int wm = wid >> 3;           // 0..1 -> row block of 32
    int wn = wid & 7;            // 0..7 -> col block of 32
    int R = wm * 32;
    int C = wn * 32;

    int a_r = (lane & 7) + ((lane >> 3) & 1) * 8;
    int a_k = ((lane >> 4) & 1) * 8;
    int b_n = (lane & 7) + ((lane >> 4) & 1) * 8;
    int b_k = ((lane >> 3) & 1) * 8;
    int g  = lane >> 2;
    int tg = lane & 3;

    int pr[4], pq[4];
#pragma unroll
    for (int it = 0; it < 4; it++) {
        int idx = tid + it * 512;
        pr[it] = idx >> 5;
        pq[it] = idx & 31;
    }

    bool is_y = (C >= 128);
    float bv0[4], bv1[4];
    if (is_y) {
#pragma unroll
        for (int nt = 0; nt < 4; nt++) {
            int yc = C - 128 + nt * 8 + tg * 2;
            bv0[nt] = __ldg(&bias[yc]);
            bv1[nt] = __ldg(&bias[yc + 1]);
        }
    }

    // ---- prologue: prefetch + convert first tile into buffer 0 ----
    float4 pf[4];
    int tile0 = blockIdx.x;
    {
        int row0 = tile0 * TILE_M;
#pragma unroll
        for (int it = 0; it < 4; it++) {
            int grow = row0 + pr[it];
            pf[it] = (tile0 < ntiles && grow < n)
                   ? *(const float4*)(h + (size_t)grow * D + pq[it] * 4)
                   : make_float4(0.f, 0.f, 0.f, 0.f);
        }
#pragma unroll
        for (int it = 0; it < 4; it++) {
            unsigned long long hi8, lo8;
            split_f4(pf[it], hi8, lo8);
            *(unsigned long long*)(smem + TF_A0_OFF + sw_off(pr[it], pq[it] * 4))       = hi8;
            *(unsigned long long*)(smem + TF_A0_OFF + sw_off(pr[it], 128 + pq[it] * 4)) = lo8;
        }
    }

    int cur = 0;
    for (int tile = tile0; tile < ntiles; tile += gridDim.x) {
        __syncthreads();
        const uint32_t sa = sbase + (cur ? TF_A1_OFF : TF_A0_OFF);
        const uint32_t sa_nxt = sbase + (cur ? TF_A0_OFF : TF_A1_OFF);
        int nxt = tile + gridDim.x;
        bool have_nxt = (nxt < ntiles);

        if (have_nxt) {
            int nrow0 = nxt * TILE_M;
#pragma unroll
            for (int it = 0; it < 4; it++) {
                int grow = nrow0 + pr[it];
                pf[it] = (grow < n)
                       ? *(const float4*)(h + (size_t)grow * D + pq[it] * 4)
                       : make_float4(0.f, 0.f, 0.f, 0.f);
            }
        }

        float acc[2][4][4];
#pragma unroll
        for (int mt = 0; mt < 2; mt++)
#pragma unroll
            for (int nt = 0; nt < 4; nt++)
#pragma unroll
                for (int i = 0; i < 4; i++) acc[mt][nt][i] = 0.f;

#pragma unroll
        for (int kc = 0; kc < 8; kc++) {
            int ka_hi = kc * 16 + a_k;
            int ka_lo = 128 + ka_hi;
            int kb_hi = kc * 16 + b_k;
            int kb_lo = 128 + kb_hi;

            uint32_t ahi[2][4], alo[2][4];
#pragma unroll
            for (int mt = 0; mt < 2; mt++) {
                uint32_t addr = sa + sw_off(R + mt * 16 + a_r, ka_hi);
                LDSM_X4(ahi[mt][0], ahi[mt][1], ahi[mt][2], ahi[mt][3], addr);
                addr = sa + sw_off(R + mt * 16 + a_r, ka_lo);
                LDSM_X4(alo[mt][0], alo[mt][1], alo[mt][2], alo[mt][3], addr);
            }
            uint32_t bhi[4][2];
#pragma unroll
            for (int p = 0; p < 2; p++) {
                uint32_t addr = sb + sw_off(C + p * 16 + b_n, kb_hi);
                uint32_t d0, d1, d2, d3;
                LDSM_X4(d0, d1, d2, d3, addr);
                bhi[p * 2][0] = d0;     bhi[p * 2][1] = d1;
                bhi[p * 2 + 1][0] = d2; bhi[p * 2 + 1][1] = d3;
            }
#pragma unroll
            for (int mt = 0; mt < 2; mt++)
#pragma unroll
                for (int nt = 0; nt < 4; nt++) {
                    MMA_BF16(acc[mt][nt], ahi[mt], bhi[nt]);
                    MMA_BF16(acc[mt][nt], alo[mt], bhi[nt]);
                }
            uint32_t blo[4][2];
#pragma unroll
            for (int p = 0; p < 2; p++) {
                uint32_t addr = sb + sw_off(C + p * 16 + b_n, kb_lo);
                uint32_t d0, d1, d2, d3;
                LDSM_X4(d0, d1, d2, d3, addr);
                blo[p * 2][0] = d0;     blo[p * 2][1] = d1;
                blo[p * 2 + 1][0] = d2; blo[p * 2 + 1][1] = d3;
            }
#pragma unroll
            for (int mt = 0; mt < 2; mt++)
#pragma unroll
                for (int nt = 0; nt < 4; nt++)
                    MMA_BF16(acc[mt][nt], ahi[mt], blo[nt]);
        }

        if (have_nxt) {
#pragma unroll
            for (int it = 0; it < 4; it++) {
                unsigned long long hi8, lo8;
                split_f4(pf[it], hi8, lo8);
                *(unsigned long long*)((char*)smem + (sa_nxt - sbase) + sw_off(pr[it], pq[it] * 4))       = hi8;
                *(unsigned long long*)((char*)smem + (sa_nxt - sbase) + sw_off(pr[it], 128 + pq[it] * 4)) = lo8;
            }
        }

        int row0 = tile * TILE_M;
#pragma unroll
        for (int mt = 0; mt < 2; mt++) {
            int r0g = row0 + R + mt * 16 + g;
            int r1g = r0g + 8;
            bool ok0 = (r0g < n), ok1 = (r1g < n);
            if (!is_y) {
#pragma unroll
                for (int nt = 0; nt < 4; nt++) {
                    int colg = C + nt * 8 + tg * 2;
                    if (ok0) *(__half2*)(zh + (size_t)r0g * D + colg) =
                        __floats2half2_rn(acc[mt][nt][0], acc[mt][nt][1]);
                    if (ok1) *(__half2*)(zh + (size_t)r1g * D + colg) =
                        __floats2half2_rn(acc[mt][nt][2], acc[mt][nt][3]);
                }
            } else {
#pragma unroll
                for (int nt = 0; nt < 4; nt++) {
                    int yc = C - 128 + nt * 8 + tg * 2;
                    if (ok0) *(float2*)(yo + (size_t)r0g * D + yc) =
                        make_float2(acc[mt][nt][0] + bv0[nt], acc[mt][nt][1] + bv1[nt]);
                    if (ok1) *(float2*)(yo + (size_t)r1g * D + yc) =
                        make_float2(acc[mt][nt][2] + bv0[nt], acc[mt][nt][3] + bv1[nt]);
                }
            }
        }
        cur ^= 1;
    }
}

// ---------------- aggregation: out[i] = act(sum zh[col] * invdeg + y) ----------
__global__ __launch_bounds__(256) void aggregate_kernel(
    const __half* __restrict__ zh, const float* __restrict__ y,
    const int* __restrict__ rowptr, const int* __restrict__ col,
    const float* __restrict__ invdeg, float* __restrict__ out,
    int n, int do_relu)
{
    int warp = (int)((blockIdx.x * blockDim.x + threadIdx.x) >> 5);
    int lane = threadIdx.x & 31;
    if (warp >= n) return;

    int beg = rowptr[warp];
    int end = rowptr[warp + 1];

    float4 acc = make_float4(0.f, 0.f, 0.f, 0.f);
    for (int e = beg; e < end; e++) {
        int s = __ldg(&col[e]);
        uint2 raw = *(const uint2*)(zh + (size_t)s * D + lane * 4);
        float2 f0 = __half22float2(*(__half2*)&raw.x);
        float2 f1 = __half22float2(*(__half2*)&raw.y);
        acc.x += f0.x; acc.y += f0.y; acc.z += f1.x; acc.w += f1.y;
    }
    float inv = invdeg[warp];
    float4 yv = *(const float4*)(y + (size_t)warp * D + lane * 4);
    float4 o;
    o.x = fmaf(acc.x, inv, yv.x);
    o.y = fmaf(acc.y, inv, yv.y);
    o.z = fmaf(acc.z, inv, yv.z);
    o.w = fmaf(acc.w, inv, yv.w);
    if (do_relu) {
        o.x = fmaxf(o.x, 0.f); o.y = fmaxf(o.y, 0.f);
        o.z = fmaxf(o.z, 0.f); o.w = fmaxf(o.w, 0.f);
    }
    *(float4*)(out + (size_t)warp * D + lane * 4) = o;
}

// ---------------- launch -------------------------------------------------------
extern "C" void kernel_launch(void* const* d_in, const int* in_sizes, int n_in,
                              void* d_out, int out_size) {
    const float* x  = (const float*)d_in[0];
    const int*   ei = (const int*)d_in[1];      // int32 (JAX downcasts int64 w/o x64)
    const float* Wl[3] = {(const float*)d_in[2], (const float*)d_in[5], (const float*)d_in[8]};
    const float* Wr[3] = {(const float*)d_in[3], (const float*)d_in[6], (const float*)d_in[9]};
    const float* bb[3] = {(const float*)d_in[4], (const float*)d_in[7], (const float*)d_in[10]};
    float* out = (float*)d_out;

    int n = in_sizes[0] / D;        // 100000
    int e = in_sizes[1] / 2;        // 1600000
    const int* src = ei;
    const int* dst = ei + e;

    float *p_y, *p_h1, *p_h2, *p_invdeg;
    __half* p_zh;
    int *p_col, *p_rowptr, *p_cursor, *p_deg, *p_bsums;
    char* p_wimg;
    cudaGetSymbolAddress((void**)&p_zh,     g_zh);
    cudaGetSymbolAddress((void**)&p_y,      g_y);
    cudaGetSymbolAddress((void**)&p_h1,     g_h1);
    cudaGetSymbolAddress((void**)&p_h2,     g_h2);
    cudaGetSymbolAddress((void**)&p_invdeg, g_invdeg);
    cudaGetSymbolAddress((void**)&p_col,    g_col);
    cudaGetSymbolAddress((void**)&p_rowptr, g_rowptr);
    cudaGetSymbolAddress((void**)&p_cursor, g_cursor);
    cudaGetSymbolAddress((void**)&p_deg,    g_deg);
    cudaGetSymbolAddress((void**)&p_bsums,  g_bsums);
    cudaGetSymbolAddress((void**)&p_wimg,   g_wimg);

    // one-time infra (no device memory involved)
    static cudaStream_t s_csr = nullptr;
    static cudaEvent_t ev_fork = nullptr, ev_join = nullptr;
    if (!s_csr) {
        cudaFuncSetAttribute(transform_mma_kernel,
                             cudaFuncAttributeMaxDynamicSharedMemorySize, TF_SMEM_SZ);
        cudaStreamCreateWithFlags(&s_csr, cudaStreamNonBlocking);
        cudaEventCreateWithFlags(&ev_fork, cudaEventDisableTiming);
        cudaEventCreateWithFlags(&ev_join, cudaEventDisableTiming);
    }

    int nb_n = (n + 255) / 256;
    int nb_e = (e + 255) / 256;
    int nb_scan = (n + SCANB - 1) / SCANB;
    int ntiles = (n + TILE_M - 1) / TILE_M;        // 1563
    int nb_ag = (n * 32 + 255) / 256;
    float* houts[3] = {p_h1, p_h2, out};

    // ---- fork: W convert (layers 1,2) + CSR build on side stream --------------
    cudaEventRecord(ev_fork, 0);
    cudaStreamWaitEvent(s_csr, ev_fork, 0);

    convert_w_kernel<<<32, 256, 0, s_csr>>>(Wl[1], Wr[1], p_wimg + 131072);
    convert_w_kernel<<<32, 256, 0, s_csr>>>(Wl[2], Wr[2], p_wimg + 2 * 131072);
    zero_deg_kernel<<<nb_n, 256, 0, s_csr>>>(p_deg, n);
    hist_kernel<<<nb_e, 256, 0, s_csr>>>(dst, p_deg, e);
    invdeg_kernel<<<nb_n, 256, 0, s_csr>>>(p_deg, p_invdeg, n);
    scanA_kernel<<<nb_scan, SCANB, 0, s_csr>>>(p_deg, p_rowptr, p_bsums, n);
    scanB_kernel<<<1, 1024, 0, s_csr>>>(p_bsums, nb_scan);
    scanC_kernel<<<nb_n, 256, 0, s_csr>>>(p_rowptr, p_cursor, p_bsums, n, e);
    scatter_kernel<<<nb_e, 256, 0, s_csr>>>(src, dst, p_cursor, p_col, e);
    cudaEventRecord(ev_join, s_csr);

    // ---- main: W convert (layer 0) + transform1 -------------------------------
    convert_w_kernel<<<32, 256>>>(Wl[0], Wr[0], p_wimg);
    transform_mma_kernel<<<148, 512, TF_SMEM_SZ>>>(x, p_wimg, bb[0],
                                                   p_zh, p_y, n, ntiles);

    // ---- join: aggregate needs CSR (and transforms 2,3 need wimg[1,2]) --------
    cudaStreamWaitEvent(0, ev_join, 0);
    aggregate_kernel<<<nb_ag, 256>>>(p_zh, p_y, p_rowptr, p_col, p_invdeg,
                                     houts[0], n, 1);
    for (int l = 1; l < 3; l++) {
        transform_mma_kernel<<<148, 512, TF_SMEM_SZ>>>(houts[l - 1],
                                                       p_wimg + (size_t)l * 131072,
                                                       bb[l], p_zh, p_y, n, ntiles);
        aggregate_kernel<<<nb_ag, 256>>>(p_zh, p_y, p_rowptr, p_col, p_invdeg,
                                         houts[l], n, (l < 2) ? 1 : 0);
    }
}

// round 15
// speedup vs baseline: 1.1171x; 1.0340x over previous
#include <cuda_runtime.h>
#include <cuda_bf16.h>
#include <cuda_fp16.h>
#include <stdint.h>

// Problem constants (fixed by the dataset)
#define NMAX   100000
#define EMAX   1600000
#define D      128
#define SCANB  1024

// ---------------- device scratch (allocation-free rule: __device__ globals) ----
__device__ __half g_zh[NMAX * D];     // fp16 message term (gathered by aggregate)
__device__ __half g_y[NMAX * D];      // fp16 root term
__device__ __half g_h1[NMAX * D];     // fp16 layer-1 activations
__device__ __half g_h2[NMAX * D];     // fp16 layer-2 activations
__device__ int   g_col[EMAX];
__device__ int   g_rowptr[NMAX + 1];
__device__ int   g_cursor[NMAX];
__device__ int   g_deg[NMAX];
__device__ float g_invdeg[NMAX];
__device__ int   g_bsums[1024];
// pre-converted, pre-swizzled W tile images (split-bf16), one per layer
__device__ __align__(16) char g_wimg[3][131072];

// ---------------- CSR build ---------------------------------------------------
__global__ void zero_deg_kernel(int* deg, int n) {
    int i = blockIdx.x * blockDim.x + threadIdx.x;
    if (i < n) deg[i] = 0;
}

__global__ void hist_kernel(const int* __restrict__ dst, int* __restrict__ deg, int e) {
    int i = blockIdx.x * blockDim.x + threadIdx.x;
    if (i < e) atomicAdd(&deg[dst[i]], 1);
}

__global__ void invdeg_kernel(const int* __restrict__ deg, float* __restrict__ invdeg, int n) {
    int i = blockIdx.x * blockDim.x + threadIdx.x;
    if (i < n) {
        int d = deg[i];
        invdeg[i] = 1.0f / (float)(d > 0 ? d : 1);
    }
}

__global__ void scanA_kernel(const int* __restrict__ deg, int* __restrict__ excl,
                             int* __restrict__ bsums, int n) {
    __shared__ int sh[SCANB];
    int tid = threadIdx.x;
    int i = blockIdx.x * SCANB + tid;
    int v = (i < n) ? deg[i] : 0;
    sh[tid] = v;
    __syncthreads();
    for (int off = 1; off < SCANB; off <<= 1) {
        int t = (tid >= off) ? sh[tid - off] : 0;
        __syncthreads();
        sh[tid] += t;
        __syncthreads();
    }
    if (i < n) excl[i] = sh[tid] - v;
    if (tid == SCANB - 1) bsums[blockIdx.x] = sh[tid];
}

__global__ void scanB_kernel(int* __restrict__ bsums, int nb) {
    __shared__ int sh[1024];
    int tid = threadIdx.x;
    int v = (tid < nb) ? bsums[tid] : 0;
    sh[tid] = v;
    __syncthreads();
    for (int off = 1; off < 1024; off <<= 1) {
        int t = (tid >= off) ? sh[tid - off] : 0;
        __syncthreads();
        sh[tid] += t;
        __syncthreads();
    }
    if (tid < nb) bsums[tid] = sh[tid] - v;
}

__global__ void scanC_kernel(int* __restrict__ rowptr, int* __restrict__ cursor,
                             const int* __restrict__ bsums, int n, int e) {
    int i = blockIdx.x * blockDim.x + threadIdx.x;
    if (i < n) {
        int r = rowptr[i] + bsums[i >> 10];
        rowptr[i] = r;
        cursor[i] = r;
    }
    if (i == 0) rowptr[n] = e;
}

__global__ void scatter_kernel(const int* __restrict__ src,
                               const int* __restrict__ dst,
                               int* __restrict__ cursor, int* __restrict__ col, int e) {
    int i = blockIdx.x * blockDim.x + threadIdx.x;
    if (i < e) {
        int d = dst[i];
        int s = src[i];
        int pos = atomicAdd(&cursor[d], 1);
        col[pos] = s;
    }
}

// ---------------- shared helpers -----------------------------------------------
__device__ __forceinline__ uint32_t sw_off(int row, int k) {
    int chunk = k >> 3;
    int swc = chunk ^ (row & 7);
    return (uint32_t)(row * 512 + swc * 16 + (k & 7) * 2);
}

__device__ __forceinline__ unsigned long long pack2x2(__nv_bfloat162 p0, __nv_bfloat162 p1) {
    unsigned int u0 = *(unsigned int*)&p0;
    unsigned int u1 = *(unsigned int*)&p1;
    return (unsigned long long)u0 | ((unsigned long long)u1 << 32);
}

__device__ __forceinline__ void split_f4(float4 v, unsigned long long& hi8,
                                         unsigned long long& lo8) {
    __nv_bfloat162 h01 = __floats2bfloat162_rn(v.x, v.y);
    __nv_bfloat162 h23 = __floats2bfloat162_rn(v.z, v.w);
    float r0 = v.x - __low2float(h01);
    float r1 = v.y - __high2float(h01);
    float r2 = v.z - __low2float(h23);
    float r3 = v.w - __high2float(h23);
    __nv_bfloat162 l01 = __floats2bfloat162_rn(r0, r1);
    __nv_bfloat162 l23 = __floats2bfloat162_rn(r2, r3);
    hi8 = pack2x2(h01, h23);
    lo8 = pack2x2(l01, l23);
}

__device__ __forceinline__ uint32_t smem_u32(const void* p) {
    uint32_t a;
    asm("{ .reg .u64 t; cvta.to.shared.u64 t, %1; cvt.u32.u64 %0, t; }" : "=r"(a) : "l"(p));
    return a;
}

#define LDSM_X4(d0, d1, d2, d3, addr) \
    asm volatile("ldmatrix.sync.aligned.m8n8.x4.shared.b16 {%0,%1,%2,%3}, [%4];" \
                 : "=r"(d0), "=r"(d1), "=r"(d2), "=r"(d3) : "r"(addr))

#define MMA_BF16(d, a, b) \
    asm volatile("mma.sync.aligned.m16n8k16.row.col.f32.bf16.bf16.f32 " \
                 "{%0,%1,%2,%3}, {%4,%5,%6,%7}, {%8,%9}, {%0,%1,%2,%3};" \
                 : "+f"((d)[0]), "+f"((d)[1]), "+f"((d)[2]), "+f"((d)[3]) \
                 : "r"((a)[0]), "r"((a)[1]), "r"((a)[2]), "r"((a)[3]), \
                   "r"((b)[0]), "r"((b)[1]))

// ---------------- W pre-convert: fp32 -> split-bf16, swizzled tile image -------
__global__ __launch_bounds__(256) void convert_w_kernel(
    const float* __restrict__ Wl, const float* __restrict__ Wr, char* __restrict__ img)
{
    int idx = blockIdx.x * blockDim.x + threadIdx.x;   // 0..8191
    if (idx >= 8192) return;
    int j = idx >> 5;
    int q = idx & 31;
    const float* srcw = (j < 128) ? (Wl + (size_t)j * D + q * 4)
                                  : (Wr + (size_t)(j - 128) * D + q * 4);
    float4 v = *(const float4*)srcw;
    unsigned long long hi8, lo8;
    split_f4(v, hi8, lo8);
    *(unsigned long long*)(img + sw_off(j, q * 4))       = hi8;
    *(unsigned long long*)(img + sw_off(j, 128 + q * 4)) = lo8;
}

// ---------------- tensor-core transform (persistent, double-buffered) ----------
// Input h may be fp32 (layer 1: x) or fp16 (layers 2,3) — h_half selects.
#define TF_A0_OFF  0
#define TF_A1_OFF  32768
#define TF_B_OFF   65536
#define TF_SMEM_SZ 196608
#define TILE_M     64

__device__ __forceinline__ float4 load_h4(const void* h, int h_half, int row, int q) {
    if (h_half) {
        uint2 r = *(const uint2*)((const __half*)h + (size_t)row * D + q * 4);
        float2 f0 = __half22float2(*(__half2*)&r.x);
        float2 f1 = __half22float2(*(__half2*)&r.y);
        return make_float4(f0.x, f0.y, f1.x, f1.y);
    }
    return *(const float4*)((const float*)h + (size_t)row * D + q * 4);
}

__global__ __launch_bounds__(512) void transform_mma_kernel(
    const void* __restrict__ h, int h_half,
    const char* __restrict__ wimg,
    const float* __restrict__ bias,
    __half* __restrict__ zh, __half* __restrict__ yo, int n, int ntiles)
{
    extern __shared__ char smem[];
    const uint32_t sbase = smem_u32(smem);
    const uint32_t sb = sbase + TF_B_OFF;
    int tid = threadIdx.x;

    // ---- load pre-converted W tile (131072 B straight copy) ----
    {
        const float4* wsrc = (const float4*)wimg;
        float4* bdst = (float4*)(smem + TF_B_OFF);
#pragma unroll
        for (int it = 0; it < 16; it++)
            bdst[tid + it * 512] = wsrc[tid + it * 512];
    }

    int wid = tid >> 5;
    int lane = tid & 31;
    int wm = wid >> 3;           // 0..1 -> row block of 32
    int wn = wid & 7;            // 0..7 -> col block of 32
    int R = wm * 32;
    int C = wn * 32;

    int a_r = (lane & 7) + ((lane >> 3) & 1) * 8;
    int a_k = ((lane >> 4) & 1) * 8;
    int b_n = (lane & 7) + ((lane >> 4) & 1) * 8;
    int b_k = ((lane >> 3) & 1) * 8;
    int g  = lane >> 2;
    int tg = lane & 3;

    int pr[4], pq[4];
#pragma unroll
    for (int it = 0; it < 4; it++) {
        int idx = tid + it * 512;
        pr[it] = idx >> 5;
        pq[it] = idx & 31;
    }

    bool is_y = (C >= 128);
    float bv0[4], bv1[4];
    if (is_y) {
#pragma unroll
        for (int nt = 0; nt < 4; nt++) {
            int yc = C - 128 + nt * 8 + tg * 2;
            bv0[nt] = __ldg(&bias[yc]);
            bv1[nt] = __ldg(&bias[yc + 1]);
        }
    }

    // ---- prologue: prefetch + convert first tile into buffer 0 ----
    float4 pf[4];
    int tile0 = blockIdx.x;
    {
        int row0 = tile0 * TILE_M;
#pragma unroll
        for (int it = 0; it < 4; it++) {
            int grow = row0 + pr[it];
            pf[it] = (tile0 < ntiles && grow < n)
                   ? load_h4(h, h_half, grow, pq[it])
                   : make_float4(0.f, 0.f, 0.f, 0.f);
        }
#pragma unroll
        for (int it = 0; it < 4; it++) {
            unsigned long long hi8, lo8;
            split_f4(pf[it], hi8, lo8);
            *(unsigned long long*)(smem + TF_A0_OFF + sw_off(pr[it], pq[it] * 4))       = hi8;
            *(unsigned long long*)(smem + TF_A0_OFF + sw_off(pr[it], 128 + pq[it] * 4)) = lo8;
        }
    }

    int cur = 0;
    for (int tile = tile0; tile < ntiles; tile += gridDim.x) {
        __syncthreads();
        const uint32_t sa = sbase + (cur ? TF_A1_OFF : TF_A0_OFF);
        const uint32_t sa_nxt = sbase + (cur ? TF_A0_OFF : TF_A1_OFF);
        int nxt = tile + gridDim.x;
        bool have_nxt = (nxt < ntiles);

        if (have_nxt) {
            int nrow0 = nxt * TILE_M;
#pragma unroll
            for (int it = 0; it < 4; it++) {
                int grow = nrow0 + pr[it];
                pf[it] = (grow < n)
                       ? load_h4(h, h_half, grow, pq[it])
                       : make_float4(0.f, 0.f, 0.f, 0.f);
            }
        }

        float acc[2][4][4];
#pragma unroll
        for (int mt = 0; mt < 2; mt++)
#pragma unroll
            for (int nt = 0; nt < 4; nt++)
#pragma unroll
                for (int i = 0; i < 4; i++) acc[mt][nt][i] = 0.f;

#pragma unroll
        for (int kc = 0; kc < 8; kc++) {
            int ka_hi = kc * 16 + a_k;
            int ka_lo = 128 + ka_hi;
            int kb_hi = kc * 16 + b_k;
            int kb_lo = 128 + kb_hi;

            uint32_t ahi[2][4], alo[2][4];
#pragma unroll
            for (int mt = 0; mt < 2; mt++) {
                uint32_t addr = sa + sw_off(R + mt * 16 + a_r, ka_hi);
                LDSM_X4(ahi[mt][0], ahi[mt][1], ahi[mt][2], ahi[mt][3], addr);
                addr = sa + sw_off(R + mt * 16 + a_r, ka_lo);
                LDSM_X4(alo[mt][0], alo[mt][1], alo[mt][2], alo[mt][3], addr);
            }
            uint32_t bhi[4][2];
#pragma unroll
            for (int p = 0; p < 2; p++) {
                uint32_t addr = sb + sw_off(C + p * 16 + b_n, kb_hi);
                uint32_t d0, d1, d2, d3;
                LDSM_X4(d0, d1, d2, d3, addr);
                bhi[p * 2][0] = d0;     bhi[p * 2][1] = d1;
                bhi[p * 2 + 1][0] = d2; bhi[p * 2 + 1][1] = d3;
            }
#pragma unroll
            for (int mt = 0; mt < 2; mt++)
#pragma unroll
                for (int nt = 0; nt < 4; nt++) {
                    MMA_BF16(acc[mt][nt], ahi[mt], bhi[nt]);
                    MMA_BF16(acc[mt][nt], alo[mt], bhi[nt]);
                }
            uint32_t blo[4][2];
#pragma unroll
            for (int p = 0; p < 2; p++) {
                uint32_t addr = sb + sw_off(C + p * 16 + b_n, kb_lo);
                uint32_t d0, d1, d2, d3;
                LDSM_X4(d0, d1, d2, d3, addr);
                blo[p * 2][0] = d0;     blo[p * 2][1] = d1;
                blo[p * 2 + 1][0] = d2; blo[p * 2 + 1][1] = d3;
            }
#pragma unroll
            for (int mt = 0; mt < 2; mt++)
#pragma unroll
                for (int nt = 0; nt < 4; nt++)
                    MMA_BF16(acc[mt][nt], ahi[mt], blo[nt]);
        }

        if (have_nxt) {
#pragma unroll
            for (int it = 0; it < 4; it++) {
                unsigned long long hi8, lo8;
                split_f4(pf[it], hi8, lo8);
                *(unsigned long long*)((char*)smem + (sa_nxt - sbase) + sw_off(pr[it], pq[it] * 4))       = hi8;
                *(unsigned long long*)((char*)smem + (sa_nxt - sbase) + sw_off(pr[it], 128 + pq[it] * 4)) = lo8;
            }
        }

        int row0 = tile * TILE_M;
#pragma unroll
        for (int mt = 0; mt < 2; mt++) {
            int r0g = row0 + R + mt * 16 + g;
            int r1g = r0g + 8;
            bool ok0 = (r0g < n), ok1 = (r1g < n);
            if (!is_y) {
#pragma unroll
                for (int nt = 0; nt < 4; nt++) {
                    int colg = C + nt * 8 + tg * 2;
                    if (ok0) *(__half2*)(zh + (size_t)r0g * D + colg) =
                        __floats2half2_rn(acc[mt][nt][0], acc[mt][nt][1]);
                    if (ok1) *(__half2*)(zh + (size_t)r1g * D + colg) =
                        __floats2half2_rn(acc[mt][nt][2], acc[mt][nt][3]);
                }
            } else {
#pragma unroll
                for (int nt = 0; nt < 4; nt++) {
                    int yc = C - 128 + nt * 8 + tg * 2;
                    if (ok0) *(__half2*)(yo + (size_t)r0g * D + yc) =
                        __floats2half2_rn(acc[mt][nt][0] + bv0[nt], acc[mt][nt][1] + bv1[nt]);
                    if (ok1) *(__half2*)(yo + (size_t)r1g * D + yc) =
                        __floats2half2_rn(acc[mt][nt][2] + bv0[nt], acc[mt][nt][3] + bv1[nt]);
                }
            }
        }
        cur ^= 1;
    }
}

// ---------------- aggregation: out = act(sum zh[col] * invdeg + y) -------------
// outh != null -> fp16 intermediate output; else fp32 final output.
__global__ __launch_bounds__(256) void aggregate_kernel(
    const __half* __restrict__ zh, const __half* __restrict__ y,
    const int* __restrict__ rowptr, const int* __restrict__ col,
    const float* __restrict__ invdeg,
    __half* __restrict__ outh, float* __restrict__ outf,
    int n, int do_relu)
{
    int warp = (int)((blockIdx.x * blockDim.x + threadIdx.x) >> 5);
    int lane = threadIdx.x & 31;
    if (warp >= n) return;

    int beg = rowptr[warp];
    int end = rowptr[warp + 1];

    float4 acc = make_float4(0.f, 0.f, 0.f, 0.f);
    for (int e = beg; e < end; e++) {
        int s = __ldg(&col[e]);
        uint2 raw = *(const uint2*)(zh + (size_t)s * D + lane * 4);
        float2 f0 = __half22float2(*(__half2*)&raw.x);
        float2 f1 = __half22float2(*(__half2*)&raw.y);
        acc.x += f0.x; acc.y += f0.y; acc.z += f1.x; acc.w += f1.y;
    }
    float inv = invdeg[warp];
    uint2 yraw = *(const uint2*)(y + (size_t)warp * D + lane * 4);
    float2 y0 = __half22float2(*(__half2*)&yraw.x);
    float2 y1 = __half22float2(*(__half2*)&yraw.y);
    float4 o;
    o.x = fmaf(acc.x, inv, y0.x);
    o.y = fmaf(acc.y, inv, y0.y);
    o.z = fmaf(acc.z, inv, y1.x);
    o.w = fmaf(acc.w, inv, y1.y);
    if (do_relu) {
        o.x = fmaxf(o.x, 0.f); o.y = fmaxf(o.y, 0.f);
        o.z = fmaxf(o.z, 0.f); o.w = fmaxf(o.w, 0.f);
    }
    if (outh) {
        uint2 w;
        __half2 p0 = __floats2half2_rn(o.x, o.y);
        __half2 p1 = __floats2half2_rn(o.z, o.w);
        w.x = *(unsigned int*)&p0;
        w.y = *(unsigned int*)&p1;
        *(uint2*)(outh + (size_t)warp * D + lane * 4) = w;
    } else {
        *(float4*)(outf + (size_t)warp * D + lane * 4) = o;
    }
}

// ---------------- launch -------------------------------------------------------
extern "C" void kernel_launch(void* const* d_in, const int* in_sizes, int n_in,
                              void* d_out, int out_size) {
    const float* x  = (const float*)d_in[0];
    const int*   ei = (const int*)d_in[1];      // int32 (JAX downcasts int64 w/o x64)
    const float* Wl[3] = {(const float*)d_in[2], (const float*)d_in[5], (const float*)d_in[8]};
    const float* Wr[3] = {(const float*)d_in[3], (const float*)d_in[6], (const float*)d_in[9]};
    const float* bb[3] = {(const float*)d_in[4], (const float*)d_in[7], (const float*)d_in[10]};
    float* out = (float*)d_out;

    int n = in_sizes[0] / D;        // 100000
    int e = in_sizes[1] / 2;        // 1600000
    const int* src = ei;
    const int* dst = ei + e;

    float *p_invdeg;
    __half *p_zh, *p_y, *p_h1, *p_h2;
    int *p_col, *p_rowptr, *p_cursor, *p_deg, *p_bsums;
    char* p_wimg;
    cudaGetSymbolAddress((void**)&p_zh,     g_zh);
    cudaGetSymbolAddress((void**)&p_y,      g_y);
    cudaGetSymbolAddress((void**)&p_h1,     g_h1);
    cudaGetSymbolAddress((void**)&p_h2,     g_h2);
    cudaGetSymbolAddress((void**)&p_invdeg, g_invdeg);
    cudaGetSymbolAddress((void**)&p_col,    g_col);
    cudaGetSymbolAddress((void**)&p_rowptr, g_rowptr);
    cudaGetSymbolAddress((void**)&p_cursor, g_cursor);
    cudaGetSymbolAddress((void**)&p_deg,    g_deg);
    cudaGetSymbolAddress((void**)&p_bsums,  g_bsums);
    cudaGetSymbolAddress((void**)&p_wimg,   g_wimg);

    // one-time infra (no device memory involved)
    static cudaStream_t s_csr = nullptr;
    static cudaEvent_t ev_fork = nullptr, ev_join = nullptr;
    if (!s_csr) {
        cudaFuncSetAttribute(transform_mma_kernel,
                             cudaFuncAttributeMaxDynamicSharedMemorySize, TF_SMEM_SZ);
        cudaStreamCreateWithFlags(&s_csr, cudaStreamNonBlocking);
        cudaEventCreateWithFlags(&ev_fork, cudaEventDisableTiming);
        cudaEventCreateWithFlags(&ev_join, cudaEventDisableTiming);
    }

    int nb_n = (n + 255) / 256;
    int nb_e = (e + 255) / 256;
    int nb_scan = (n + SCANB - 1) / SCANB;
    int ntiles = (n + TILE_M - 1) / TILE_M;        // 1563
    int nb_ag = (n * 32 + 255) / 256;

    // ---- fork: CSR build on side stream ----
    cudaEventRecord(ev_fork, 0);
    cudaStreamWaitEvent(s_csr, ev_fork, 0);
    zero_deg_kernel<<<nb_n, 256, 0, s_csr>>>(p_deg, n);
    hist_kernel<<<nb_e, 256, 0, s_csr>>>(dst, p_deg, e);
    invdeg_kernel<<<nb_n, 256, 0, s_csr>>>(p_deg, p_invdeg, n);
    scanA_kernel<<<nb_scan, SCANB, 0, s_csr>>>(p_deg, p_rowptr, p_bsums, n);
    scanB_kernel<<<1, 1024, 0, s_csr>>>(p_bsums, nb_scan);
    scanC_kernel<<<nb_n, 256, 0, s_csr>>>(p_rowptr, p_cursor, p_bsums, n, e);
    scatter_kernel<<<nb_e, 256, 0, s_csr>>>(src, dst, p_cursor, p_col, e);
    cudaEventRecord(ev_join, s_csr);

    // ---- main: W converts + transform1 ----
    for (int l = 0; l < 3; l++)
        convert_w_kernel<<<32, 256>>>(Wl[l], Wr[l], p_wimg + (size_t)l * 131072);
    transform_mma_kernel<<<148, 512, TF_SMEM_SZ>>>(x, 0, p_wimg, bb[0],
                                                   p_zh, p_y, n, ntiles);

    // ---- join: aggregate needs CSR ----
    cudaStreamWaitEvent(0, ev_join, 0);
    aggregate_kernel<<<nb_ag, 256>>>(p_zh, p_y, p_rowptr, p_col, p_invdeg,
                                     p_h1, nullptr, n, 1);
    transform_mma_kernel<<<148, 512, TF_SMEM_SZ>>>(p_h1, 1, p_wimg + 131072, bb[1],
                                                   p_zh, p_y, n, ntiles);
    aggregate_kernel<<<nb_ag, 256>>>(p_zh, p_y, p_rowptr, p_col, p_invdeg,
                                     p_h2, nullptr, n, 1);
    transform_mma_kernel<<<148, 512, TF_SMEM_SZ>>>(p_h2, 1, p_wimg + 2 * 131072, bb[2],
                                                   p_zh, p_y, n, ntiles);
    aggregate_kernel<<<nb_ag, 256>>>(p_zh, p_y, p_rowptr, p_col, p_invdeg,
                                     nullptr, out, n, 0);
}